// round 6
// baseline (speedup 1.0000x reference)
#include <cuda_runtime.h>
#include <stdint.h>

// Problem constants
#define BATCH 4
#define NPTS  65536     // power of two: >>16 / &0xFFFF tricks
#define KNB   16
#define HID   64

// Scratch: xyz-interleaved positions (float4 = xyz + pad) for 1-load gathers.
// 4 * 65536 * 16B = 16.75 MB -> L2-resident on GB300 (126 MB L2).
__device__ float4 g_pos_t[BATCH * NPTS];

// idx dtype flag: 1 if the idx buffer is genuine int64, 0 if int32.
__device__ int g_idx_is_i64;

// ---------------------------------------------------------------------------
// Kernel 1: transpose pos (B,3,N) -> (B*N) float4 xyz-interleaved, AND (block 0
// only) probe the idx dtype. idx values < 65536, so if the buffer is int64 every
// odd 32-bit word is zero; 1024 samples all-zero <=> int64. Reads first 8 KB ->
// in-bounds under either dtype. Stream order guarantees main sees the flag.
// ---------------------------------------------------------------------------
__global__ void __launch_bounds__(256) transpose_probe_kernel(
    const float* __restrict__ pos,
    const int*   __restrict__ idx_as_i32)
{
    if (blockIdx.x == 0) {
        int nz = 0;
        #pragma unroll
        for (int i = threadIdx.x; i < 1024; i += 256) nz |= idx_as_i32[2 * i + 1];
        nz = __syncthreads_or(nz);
        if (threadIdx.x == 0) g_idx_is_i64 = (nz == 0) ? 1 : 0;
    }
    int i = blockIdx.x * 256 + threadIdx.x;     // exact grid, no bounds check
    int b = i >> 16;
    int n = i & (NPTS - 1);
    const float* p = pos + (size_t)b * 3 * NPTS;
    g_pos_t[i] = make_float4(__ldg(p + n),
                             __ldg(p + NPTS + n),
                             __ldg(p + 2 * NPTS + n), 0.0f);
}

// ---------------------------------------------------------------------------
// Kernel 2: main. 4 lanes per point, 4 neighbors per lane (MLP=4 on gathers).
//   - idx:  int32 -> one LDG.128 / lane; int64 -> two LDG.128 / lane (coalesced)
//   - dist: one LDG.128 / lane
//   - gather: 4 independent LDG.128 from g_pos_t (random, L2-resident)
//   - max: in-thread over 4, then 2-step shfl.xor butterfly over the 4 lanes
//   - GEMV 10x64: lane l computes output columns [16l, 16l+16)
//   - store: staged in smem, cooperative fully-coalesced float4 writeout
// 256 threads/block = 64 points/block -> grid 4096.
// ---------------------------------------------------------------------------
__global__ void __launch_bounds__(256) point_embed_kernel(
    const void*  __restrict__ idx_raw,
    const float* __restrict__ dist,
    const float* __restrict__ W,
    const float* __restrict__ bias,
    float*       __restrict__ out)
{
    __shared__ float  sW[10 * HID];          // 2560 B
    __shared__ float  sB[HID];               //  256 B
    __shared__ float4 sOut[64 * (HID / 4)];  // 16 KB: 64 points x 64 floats

    const int tid = threadIdx.x;
    const int l   = tid & 3;                       // lane within point (0..3)
    const int g   = blockIdx.x * 64 + (tid >> 2);  // global point id (b*N+n)
    const int b   = g >> 16;

    // ---- issue all long-latency loads first (idx -> 4 gathers, MLP=4) ------
    int j0, j1, j2, j3;
    if (g_idx_is_i64) {
        const longlong2* p = ((const longlong2*)idx_raw) + ((size_t)g * 8 + 2 * l);
        longlong2 a = __ldg(p);
        longlong2 c2 = __ldg(p + 1);
        j0 = (int)a.x;  j1 = (int)a.y;  j2 = (int)c2.x;  j3 = (int)c2.y;
    } else {
        int4 a = __ldg(((const int4*)idx_raw) + ((size_t)g * 4 + l));
        j0 = a.x;  j1 = a.y;  j2 = a.z;  j3 = a.w;
    }
    const float4 dk = __ldg(((const float4*)dist) + ((size_t)g * 4 + l));

    const int base = b << 16;
    const float4 n0 = __ldg(&g_pos_t[base + j0]);
    const float4 n1 = __ldg(&g_pos_t[base + j1]);
    const float4 n2 = __ldg(&g_pos_t[base + j2]);
    const float4 n3 = __ldg(&g_pos_t[base + j3]);
    const float4 c  = __ldg(&g_pos_t[g]);          // broadcast across 4 lanes

    // ---- stage W/b while loads are in flight -------------------------------
    #pragma unroll
    for (int i = tid; i < 10 * HID; i += 256) sW[i] = __ldg(W + i);
    if (tid < HID) sB[tid] = __ldg(bias + tid);

    // ---- in-thread max over the 4 neighbors --------------------------------
    float v3 = fmaxf(fmaxf(n0.x, n1.x), fmaxf(n2.x, n3.x));
    float v4 = fmaxf(fmaxf(n0.y, n1.y), fmaxf(n2.y, n3.y));
    float v5 = fmaxf(fmaxf(n0.z, n1.z), fmaxf(n2.z, n3.z));
    // max(c - n) = c - min(n)
    float m6 = fminf(fminf(n0.x, n1.x), fminf(n2.x, n3.x));
    float m7 = fminf(fminf(n0.y, n1.y), fminf(n2.y, n3.y));
    float m8 = fminf(fminf(n0.z, n1.z), fminf(n2.z, n3.z));
    float v9 = fmaxf(fmaxf(dk.x, dk.y), fmaxf(dk.z, dk.w));

    // ---- butterfly across the 4 lanes of this point ------------------------
    #pragma unroll
    for (int s = 1; s < 4; s <<= 1) {
        v3 = fmaxf(v3, __shfl_xor_sync(0xffffffffu, v3, s));
        v4 = fmaxf(v4, __shfl_xor_sync(0xffffffffu, v4, s));
        v5 = fmaxf(v5, __shfl_xor_sync(0xffffffffu, v5, s));
        m6 = fminf(m6, __shfl_xor_sync(0xffffffffu, m6, s));
        m7 = fminf(m7, __shfl_xor_sync(0xffffffffu, m7, s));
        m8 = fminf(m8, __shfl_xor_sync(0xffffffffu, m8, s));
        v9 = fmaxf(v9, __shfl_xor_sync(0xffffffffu, v9, s));
    }

    float f[10];
    f[0] = c.x;        f[1] = c.y;        f[2] = c.z;
    f[3] = v3;         f[4] = v4;         f[5] = v5;
    f[6] = c.x - m6;   f[7] = c.y - m7;   f[8] = c.z - m8;   f[9] = v9;

    __syncthreads();   // sW/sB ready

    // ---- GEMV: lane l owns output columns [16l, 16l+16) --------------------
    const float4* sW4 = (const float4*)sW;   // [10][16] float4
    const float4* sB4 = (const float4*)sB;   // [16] float4
    float4 acc0 = sB4[4 * l + 0];
    float4 acc1 = sB4[4 * l + 1];
    float4 acc2 = sB4[4 * l + 2];
    float4 acc3 = sB4[4 * l + 3];
    #pragma unroll
    for (int cc = 0; cc < 10; cc++) {
        const float fc = f[cc];
        float4 w0 = sW4[cc * 16 + 4 * l + 0];
        float4 w1 = sW4[cc * 16 + 4 * l + 1];
        float4 w2 = sW4[cc * 16 + 4 * l + 2];
        float4 w3 = sW4[cc * 16 + 4 * l + 3];
        acc0.x = fmaf(fc, w0.x, acc0.x); acc0.y = fmaf(fc, w0.y, acc0.y);
        acc0.z = fmaf(fc, w0.z, acc0.z); acc0.w = fmaf(fc, w0.w, acc0.w);
        acc1.x = fmaf(fc, w1.x, acc1.x); acc1.y = fmaf(fc, w1.y, acc1.y);
        acc1.z = fmaf(fc, w1.z, acc1.z); acc1.w = fmaf(fc, w1.w, acc1.w);
        acc2.x = fmaf(fc, w2.x, acc2.x); acc2.y = fmaf(fc, w2.y, acc2.y);
        acc2.z = fmaf(fc, w2.z, acc2.z); acc2.w = fmaf(fc, w2.w, acc2.w);
        acc3.x = fmaf(fc, w3.x, acc3.x); acc3.y = fmaf(fc, w3.y, acc3.y);
        acc3.z = fmaf(fc, w3.z, acc3.z); acc3.w = fmaf(fc, w3.w, acc3.w);
    }
    acc0.x = fmaxf(acc0.x, 0.f); acc0.y = fmaxf(acc0.y, 0.f);
    acc0.z = fmaxf(acc0.z, 0.f); acc0.w = fmaxf(acc0.w, 0.f);
    acc1.x = fmaxf(acc1.x, 0.f); acc1.y = fmaxf(acc1.y, 0.f);
    acc1.z = fmaxf(acc1.z, 0.f); acc1.w = fmaxf(acc1.w, 0.f);
    acc2.x = fmaxf(acc2.x, 0.f); acc2.y = fmaxf(acc2.y, 0.f);
    acc2.z = fmaxf(acc2.z, 0.f); acc2.w = fmaxf(acc2.w, 0.f);
    acc3.x = fmaxf(acc3.x, 0.f); acc3.y = fmaxf(acc3.y, 0.f);
    acc3.z = fmaxf(acc3.z, 0.f); acc3.w = fmaxf(acc3.w, 0.f);

    // stage into smem (point-major), then fully-coalesced cooperative store
    const int p16 = (tid >> 2) * 16 + 4 * l;
    sOut[p16 + 0] = acc0;
    sOut[p16 + 1] = acc1;
    sOut[p16 + 2] = acc2;
    sOut[p16 + 3] = acc3;
    __syncthreads();

    float4* out4 = (float4*)out + (size_t)blockIdx.x * 1024;
    #pragma unroll
    for (int u = 0; u < 4; u++)
        out4[u * 256 + tid] = sOut[u * 256 + tid];
}

// ---------------------------------------------------------------------------
extern "C" void kernel_launch(void* const* d_in, const int* in_sizes, int n_in,
                              void* d_out, int out_size) {
    const float* pos  = (const float*)d_in[0];   // (4, 3, 65536) f32
    const void*  idx  = d_in[1];                 // (4, 65536, 16) int64-or-int32
    const float* dist = (const float*)d_in[2];   // (4, 65536, 16) f32
    const float* W    = (const float*)d_in[3];   // (10, 64) f32
    const float* bias = (const float*)d_in[4];   // (64,) f32
    float* out = (float*)d_out;                  // (4, 65536, 64) f32

    (void)in_sizes; (void)n_in; (void)out_size;

    transpose_probe_kernel<<<(BATCH * NPTS) / 256, 256>>>(pos, (const int*)idx);
    point_embed_kernel<<<(BATCH * NPTS) / 64, 256>>>(idx, dist, W, bias, out);
}

// round 7
// speedup vs baseline: 1.4130x; 1.4130x over previous
#include <cuda_runtime.h>
#include <stdint.h>

// Problem constants
#define BATCH 4
#define NPTS  65536     // power of two: >>16 / &0xFFFF tricks
#define KNB   16
#define HID   64

// Scratch: xyz-interleaved positions (float4 = xyz + pad) for 1-load gathers.
// 4 * 65536 * 16B = 16.75 MB -> L2-resident on GB300 (126 MB L2).
__device__ float4 g_pos_t[BATCH * NPTS];

// idx dtype flag: 1 if the idx buffer is genuine int64, 0 if int32.
__device__ int g_idx_is_i64;

// ---------------------------------------------------------------------------
// Kernel 1: transpose pos (B,3,N) -> (B*N) float4 xyz-interleaved, AND (block 0
// only) probe the idx dtype. idx values < 65536, so if the buffer is int64 every
// odd 32-bit word is zero; 1024 samples all-zero <=> int64. Reads first 8 KB ->
// in-bounds under either dtype. Stream order guarantees main sees the flag.
// ---------------------------------------------------------------------------
__global__ void __launch_bounds__(256) transpose_probe_kernel(
    const float* __restrict__ pos,
    const int*   __restrict__ idx_as_i32)
{
    if (blockIdx.x == 0) {
        int nz = 0;
        #pragma unroll
        for (int i = threadIdx.x; i < 1024; i += 256) nz |= idx_as_i32[2 * i + 1];
        nz = __syncthreads_or(nz);
        if (threadIdx.x == 0) g_idx_is_i64 = (nz == 0) ? 1 : 0;
    }
    int i = blockIdx.x * 256 + threadIdx.x;     // exact grid, no bounds check
    int b = i >> 16;
    int n = i & (NPTS - 1);
    const float* p = pos + (size_t)b * 3 * NPTS;
    g_pos_t[i] = make_float4(__ldg(p + n),
                             __ldg(p + NPTS + n),
                             __ldg(p + 2 * NPTS + n), 0.0f);
}

// ---------------------------------------------------------------------------
// Kernel 2: main. 16 lanes per point, 2 points per thread (gA and gB = gA+16).
// L1tex-wavefront-minimal design (measured: L1=88% is the bottleneck):
//   - idx/dist: warp reads 128B contiguous per point -> 1 wf each (int32)
//   - gather:   1 scattered LDG.128 per (point,k) -- the irreducible cost
//   - max over K: shfl.xor butterfly inside each 16-lane half, both points
//   - GEMV 10x64: W float4 loaded ONCE per thread, FMA'd into both points'
//     accumulators (halves GEMV smem wavefronts per point vs R3)
//   - store: direct float4, each warp-half writes 256B contiguous (coalesced)
// 256 threads/block = 32 points/block -> grid 8192. No smem staging, 1 sync.
// ---------------------------------------------------------------------------
__global__ void __launch_bounds__(256) point_embed_kernel(
    const void*  __restrict__ idx_raw,
    const float* __restrict__ dist,
    const float* __restrict__ W,
    const float* __restrict__ bias,
    float*       __restrict__ out)
{
    __shared__ float sW[10 * HID];   // 2560 B
    __shared__ float sB[HID];        //  256 B

    const int tid = threadIdx.x;
    const int w   = tid >> 5;            // warp 0..7
    const int kl  = tid & 15;            // neighbor slot / column group
    const int h   = (tid >> 4) & 1;      // half within warp
    const int gA  = blockIdx.x * 32 + 2 * w + h;   // point A
    const int gB  = gA + 16;                       // point B (same batch:
                                                   // 65536 % 32 == 0)
    const int base = (gA >> 16) << 16;   // batch base in g_pos_t

    // ---- issue long-latency loads first ------------------------------------
    int jA, jB;
    if (g_idx_is_i64) {
        jA = (int)__ldg(((const long long*)idx_raw) + (((size_t)gA) << 4) + kl);
        jB = (int)__ldg(((const long long*)idx_raw) + (((size_t)gB) << 4) + kl);
    } else {
        jA = __ldg(((const int*)idx_raw) + (((size_t)gA) << 4) + kl);
        jB = __ldg(((const int*)idx_raw) + (((size_t)gB) << 4) + kl);
    }
    const float dA = __ldg(dist + (((size_t)gA) << 4) + kl);
    const float dB = __ldg(dist + (((size_t)gB) << 4) + kl);

    // ---- stage W/b while idx loads are in flight ---------------------------
    #pragma unroll
    for (int i = tid; i < 10 * HID; i += 256) sW[i] = __ldg(W + i);
    if (tid < HID) sB[tid] = __ldg(bias + tid);

    // ---- gathers (scattered, L2-resident; MLP=2) + center loads ------------
    const float4 nA = __ldg(&g_pos_t[base + jA]);
    const float4 nB = __ldg(&g_pos_t[base + jB]);
    const float4 cA = __ldg(&g_pos_t[gA]);
    const float4 cB = __ldg(&g_pos_t[gB]);

    // ---- per-k candidates; max(c-n) = c - min(n) ---------------------------
    float A3 = nA.x, A4 = nA.y, A5 = nA.z;          // max(n)
    float A6 = nA.x, A7 = nA.y, A8 = nA.z;          // min(n)
    float A9 = dA;                                   // max(d)
    float B3 = nB.x, B4 = nB.y, B5 = nB.z;
    float B6 = nB.x, B7 = nB.y, B8 = nB.z;
    float B9 = dB;

    // butterfly over the 16 lanes of each half (xor < 16 stays inside half)
    #pragma unroll
    for (int s = 1; s < 16; s <<= 1) {
        A3 = fmaxf(A3, __shfl_xor_sync(0xffffffffu, A3, s));
        A4 = fmaxf(A4, __shfl_xor_sync(0xffffffffu, A4, s));
        A5 = fmaxf(A5, __shfl_xor_sync(0xffffffffu, A5, s));
        A6 = fminf(A6, __shfl_xor_sync(0xffffffffu, A6, s));
        A7 = fminf(A7, __shfl_xor_sync(0xffffffffu, A7, s));
        A8 = fminf(A8, __shfl_xor_sync(0xffffffffu, A8, s));
        A9 = fmaxf(A9, __shfl_xor_sync(0xffffffffu, A9, s));
        B3 = fmaxf(B3, __shfl_xor_sync(0xffffffffu, B3, s));
        B4 = fmaxf(B4, __shfl_xor_sync(0xffffffffu, B4, s));
        B5 = fmaxf(B5, __shfl_xor_sync(0xffffffffu, B5, s));
        B6 = fminf(B6, __shfl_xor_sync(0xffffffffu, B6, s));
        B7 = fminf(B7, __shfl_xor_sync(0xffffffffu, B7, s));
        B8 = fminf(B8, __shfl_xor_sync(0xffffffffu, B8, s));
        B9 = fmaxf(B9, __shfl_xor_sync(0xffffffffu, B9, s));
    }

    float fA[10], fB[10];
    fA[0] = cA.x;       fA[1] = cA.y;       fA[2] = cA.z;
    fA[3] = A3;         fA[4] = A4;         fA[5] = A5;
    fA[6] = cA.x - A6;  fA[7] = cA.y - A7;  fA[8] = cA.z - A8;  fA[9] = A9;
    fB[0] = cB.x;       fB[1] = cB.y;       fB[2] = cB.z;
    fB[3] = B3;         fB[4] = B4;         fB[5] = B5;
    fB[6] = cB.x - B6;  fB[7] = cB.y - B7;  fB[8] = cB.z - B8;  fB[9] = B9;

    __syncthreads();   // sW/sB ready

    // ---- GEMV: lane kl owns cols [4kl,4kl+4); W loaded once for BOTH points
    const float4* sW4 = (const float4*)sW;   // [10][16] float4
    const float4* sB4 = (const float4*)sB;   // [16] float4
    float4 aA = sB4[kl];
    float4 aB = aA;
    #pragma unroll
    for (int cc = 0; cc < 10; cc++) {
        const float4 wv = sW4[cc * 16 + kl];
        const float xA = fA[cc], xB = fB[cc];
        aA.x = fmaf(xA, wv.x, aA.x); aA.y = fmaf(xA, wv.y, aA.y);
        aA.z = fmaf(xA, wv.z, aA.z); aA.w = fmaf(xA, wv.w, aA.w);
        aB.x = fmaf(xB, wv.x, aB.x); aB.y = fmaf(xB, wv.y, aB.y);
        aB.z = fmaf(xB, wv.z, aB.z); aB.w = fmaf(xB, wv.w, aB.w);
    }
    aA.x = fmaxf(aA.x, 0.f); aA.y = fmaxf(aA.y, 0.f);
    aA.z = fmaxf(aA.z, 0.f); aA.w = fmaxf(aA.w, 0.f);
    aB.x = fmaxf(aB.x, 0.f); aB.y = fmaxf(aB.y, 0.f);
    aB.z = fmaxf(aB.z, 0.f); aB.w = fmaxf(aB.w, 0.f);

    // direct coalesced stores: each 16-lane half writes 256B contiguous
    ((float4*)out)[(size_t)gA * (HID / 4) + kl] = aA;
    ((float4*)out)[(size_t)gB * (HID / 4) + kl] = aB;
}

// ---------------------------------------------------------------------------
extern "C" void kernel_launch(void* const* d_in, const int* in_sizes, int n_in,
                              void* d_out, int out_size) {
    const float* pos  = (const float*)d_in[0];   // (4, 3, 65536) f32
    const void*  idx  = d_in[1];                 // (4, 65536, 16) int64-or-int32
    const float* dist = (const float*)d_in[2];   // (4, 65536, 16) f32
    const float* W    = (const float*)d_in[3];   // (10, 64) f32
    const float* bias = (const float*)d_in[4];   // (64,) f32
    float* out = (float*)d_out;                  // (4, 65536, 64) f32

    (void)in_sizes; (void)n_in; (void)out_size;

    transpose_probe_kernel<<<(BATCH * NPTS) / 256, 256>>>(pos, (const int*)idx);
    point_embed_kernel<<<(BATCH * NPTS) / 32, 256>>>(idx, dist, W, bias, out);
}